// round 4
// baseline (speedup 1.0000x reference)
#include <cuda_runtime.h>
#include <cstddef>

namespace {
constexpr int Bsz = 512, Tsz = 1024, Hs = 64;
}

using ull = unsigned long long;

__device__ __forceinline__ void unpack2(ull v, float& lo, float& hi) {
    asm("mov.b64 {%0,%1},%2;" : "=f"(lo), "=f"(hi) : "l"(v));
}
__device__ __forceinline__ ull ffma2(ull a, ull b, ull c) {
    ull d;
    asm("fma.rn.f32x2 %0,%1,%2,%3;" : "=l"(d) : "l"(a), "l"(b), "l"(c));
    return d;
}
__device__ __forceinline__ float fast_ex2(float x) {
    float r; asm("ex2.approx.f32 %0,%1;" : "=f"(r) : "f"(x)); return r;
}
__device__ __forceinline__ float fast_rcp(float x) {
    float r; asm("rcp.approx.f32 %0,%1;" : "=f"(r) : "f"(x)); return r;
}
__device__ __forceinline__ float fsigmoid(float x) {
    return fast_rcp(1.0f + fast_ex2(-1.44269504f * x));
}
__device__ __forceinline__ float ftanh(float x) {
    float ax = fabsf(x);
    float t  = fast_ex2(-2.88539008f * ax);          // exp(-2|x|)
    float y  = (1.0f - t) * fast_rcp(1.0f + t);
    return copysignf(y, x);
}

// ---------------------------------------------------------------------------
// Fully fused 2-layer GRU, ONE barrier per timestep.
// Grid 128 x 384; CTA owns 4 batch rows. Thread = (m=tx>>7, j, half).
// Skew at step s:
//   m=0 : dot Whh0.h1[s-1] (smem, parity s&1)  -> combine -> h1[s]
//         (h1prev lives in registers; writes smem parity (s&1)^1)
//   m=1 : dot Wih1.h1[s-1] = gx1[s-1]          -> sh_xa[s&1] (+biases)
//   m=2 : dot Whh1.h2[s-3] (smem)              -> combine with sh_xa[(s&1)^1]
//         (= gx1[s-2]) -> h2[s-2] -> global out (h2prev in registers)
// Every cross-thread dependency crosses exactly one end-of-step barrier, so
// gate math (MUFU chains) of m=0/m=2 issues concurrently with other warps'
// FFMA2 streams. Combines are computed redundantly by both k-halves (identical
// post-shfl sums); smem/global stores predicated to half 0.
// ---------------------------------------------------------------------------
__global__ void __launch_bounds__(384, 1) gru_fused(
    const float* __restrict__ x,
    const float* __restrict__ W_ih0, const float* __restrict__ W_hh0,
    const float* __restrict__ b_ih0, const float* __restrict__ b_hh0,
    const float* __restrict__ W_ih1, const float* __restrict__ W_hh1,
    const float* __restrict__ b_ih1, const float* __restrict__ b_hh1,
    float* __restrict__ outp,        // (B,T,64)
    float* __restrict__ finalp)      // (B,64)
{
    __shared__ float sh_h1[2][4][2][36];   // [parity][row][half][32+pad]
    __shared__ float sh_h2[2][4][2][36];
    __shared__ float sh_xa[2][4][3][64];   // [parity][row][gate][j]
    __shared__ float sh_x [2][4][3];       // [parity][row][c]

    const int tx   = threadIdx.x;
    const int m    = tx >> 7;            // 0: Whh0, 1: Wih1, 2: Whh1
    const int lr   = tx & 127;
    const int half = lr & 1;
    const int j    = lr >> 1;            // output unit 0..63
    const int kb   = half * 32;

    // 3 gate-rows (j, j+64, j+128) x 32-k-half, packed f32x2
    const float* __restrict__ Wm = (m == 0) ? W_hh0 : (m == 1) ? W_ih1 : W_hh1;
    ull w2[48];
    const ull* __restrict__ Wll = reinterpret_cast<const ull*>(Wm);
#pragma unroll
    for (int g3 = 0; g3 < 3; g3++) {
        const int g = j + g3 * 64;
#pragma unroll
        for (int kk = 0; kk < 16; kk++)
            w2[g3 * 16 + kk] = Wll[(g * 64 + kb) / 2 + kk];
    }

    float wi0[9];
    float ba = 0.f, bb_ = 0.f, bc = 0.f, bd = 0.f;
    if (m == 0) {
#pragma unroll
        for (int g3 = 0; g3 < 3; g3++)
#pragma unroll
            for (int c = 0; c < 3; c++)
                wi0[g3 * 3 + c] = W_ih0[(j + g3 * 64) * 3 + c];
        ba  = b_ih0[j]       + b_hh0[j];
        bb_ = b_ih0[j + 64]  + b_hh0[j + 64];
        bc  = b_ih0[j + 128];
        bd  = b_hh0[j + 128];
    } else if (m == 1) {
        ba  = b_ih1[j]       + b_hh1[j];
        bb_ = b_ih1[j + 64]  + b_hh1[j + 64];
        bc  = b_ih1[j + 128];
    } else {
        bd  = b_hh1[j + 128];
    }

    // zero state buffers (h[-1] = 0 on both parities)
    for (int i = tx; i < 2 * 4 * 2 * 36; i += 384) {
        reinterpret_cast<float*>(sh_h1)[i] = 0.f;
        reinterpret_cast<float*>(sh_h2)[i] = 0.f;
    }
    const int row4 = blockIdx.x * 4;
    // prestage x[0] into parity 0
    if (m == 1 && half == 1 && j < 3) {
#pragma unroll
        for (int r = 0; r < 4; r++)
            sh_x[0][r][j] = __ldg(&x[((size_t)(row4 + r) * Tsz + 0) * 3 + j]);
    }
    __syncthreads();

    float hp[4] = {0.f, 0.f, 0.f, 0.f};   // h1prev (m=0) / h2prev (m=2)
    float prA[4], pzA[4], pnA[4];

    for (int s = 0; s < Tsz + 2; s++) {
        const int buf = s & 1;

        // ---- three GEMVs over 4 rows (dense FFMA2 stream) ----
        const float* __restrict__ shsrc =
            (m == 2) ? &sh_h2[buf][0][half][0] : &sh_h1[buf][0][half][0];
#pragma unroll
        for (int r = 0; r < 4; r++) {
            const ulonglong2* __restrict__ hb =
                reinterpret_cast<const ulonglong2*>(shsrc + r * 2 * 36);
            ull a0 = 0ull, a1 = 0ull, a2 = 0ull;
#pragma unroll
            for (int i = 0; i < 8; i++) {
                const ulonglong2 h4 = hb[i];               // LDS.128
                a0 = ffma2(h4.x, w2[2 * i],          a0);
                a0 = ffma2(h4.y, w2[2 * i + 1],      a0);
                a1 = ffma2(h4.x, w2[16 + 2 * i],     a1);
                a1 = ffma2(h4.y, w2[16 + 2 * i + 1], a1);
                a2 = ffma2(h4.x, w2[32 + 2 * i],     a2);
                a2 = ffma2(h4.y, w2[32 + 2 * i + 1], a2);
            }
            float l, h;
            unpack2(a0, l, h); float pr = l + h;
            unpack2(a1, l, h); float pz = l + h;
            unpack2(a2, l, h); float pn = l + h;
            pr += __shfl_xor_sync(0xffffffffu, pr, 1);
            pz += __shfl_xor_sync(0xffffffffu, pz, 1);
            pn += __shfl_xor_sync(0xffffffffu, pn, 1);
            prA[r] = pr; pzA[r] = pz; pnA[r] = pn;
        }

        // ---- per-m epilogue (no barrier in between; overlaps across warps) --
        if (m == 0) {
            if (s < Tsz) {
#pragma unroll
                for (int r = 0; r < 4; r++) {
                    const float x0 = sh_x[buf][r][0];
                    const float x1 = sh_x[buf][r][1];
                    const float x2 = sh_x[buf][r][2];
                    const float xar = fmaf(x2, wi0[2], fmaf(x1, wi0[1], fmaf(x0, wi0[0], ba)));
                    const float xaz = fmaf(x2, wi0[5], fmaf(x1, wi0[4], fmaf(x0, wi0[3], bb_)));
                    const float xan = fmaf(x2, wi0[8], fmaf(x1, wi0[7], fmaf(x0, wi0[6], bc)));
                    const float rr = fsigmoid(xar + prA[r]);
                    const float zz = fsigmoid(xaz + pzA[r]);
                    const float nn = ftanh(fmaf(rr, pnA[r] + bd, xan));
                    const float hn = fmaf(zz, hp[r] - nn, nn);
                    hp[r] = hn;
                    if (half == 0)
                        sh_h1[buf ^ 1][r][j >> 5][j & 31] = hn;
                }
            }
        } else if (m == 1) {
            if (half == 0 && s >= 1 && s <= Tsz) {
#pragma unroll
                for (int r = 0; r < 4; r++) {
                    sh_xa[buf][r][0][j] = prA[r] + ba;
                    sh_xa[buf][r][1][j] = pzA[r] + bb_;
                    sh_xa[buf][r][2][j] = pnA[r] + bc;
                }
            }
            // stage x[s+1] (parity (s+1)&1), consumed by m=0 next step
            if (half == 1 && j < 3 && s + 1 < Tsz) {
#pragma unroll
                for (int r = 0; r < 4; r++)
                    sh_x[buf ^ 1][r][j] =
                        __ldg(&x[((size_t)(row4 + r) * Tsz + (s + 1)) * 3 + j]);
            }
        } else {  // m == 2
            if (s >= 2) {
                const int tau = s - 2;
#pragma unroll
                for (int r = 0; r < 4; r++) {
                    const float xar = sh_xa[buf ^ 1][r][0][j];
                    const float xaz = sh_xa[buf ^ 1][r][1][j];
                    const float xan = sh_xa[buf ^ 1][r][2][j];
                    const float rr = fsigmoid(xar + prA[r]);
                    const float zz = fsigmoid(xaz + pzA[r]);
                    const float nn = ftanh(fmaf(rr, pnA[r] + bd, xan));
                    const float hn = fmaf(zz, hp[r] - nn, nn);
                    hp[r] = hn;
                    if (half == 0) {
                        sh_h2[buf ^ 1][r][j >> 5][j & 31] = hn;
                        outp[((size_t)(row4 + r) * Tsz + tau) * Hs + j] = hn;
                        if (tau == Tsz - 1)
                            finalp[(row4 + r) * Hs + j] = hn;
                    }
                }
            }
        }
        __syncthreads();     // the ONLY barrier per step
    }
}

// ---------------------------------------------------------------------------
extern "C" void kernel_launch(void* const* d_in, const int* in_sizes, int n_in,
                              void* d_out, int out_size)
{
    (void)in_sizes; (void)n_in; (void)out_size;
    const float* x     = (const float*)d_in[0];
    const float* W_ih0 = (const float*)d_in[1];
    const float* W_hh0 = (const float*)d_in[2];
    const float* b_ih0 = (const float*)d_in[3];
    const float* b_hh0 = (const float*)d_in[4];
    const float* W_ih1 = (const float*)d_in[5];
    const float* W_hh1 = (const float*)d_in[6];
    const float* b_ih1 = (const float*)d_in[7];
    const float* b_hh1 = (const float*)d_in[8];

    float* out    = (float*)d_out;
    float* finalh = out + (size_t)Bsz * Tsz * Hs;

    gru_fused<<<128, 384>>>(x, W_ih0, W_hh0, b_ih0, b_hh0,
                            W_ih1, W_hh1, b_ih1, b_hh1, out, finalh);
}

// round 5
// speedup vs baseline: 1.3897x; 1.3897x over previous
#include <cuda_runtime.h>
#include <cstddef>

namespace {
constexpr int Bsz = 512, Tsz = 1024, Hs = 64, R = 4;
}

using ull = unsigned long long;

__device__ __forceinline__ void unpack2(ull v, float& lo, float& hi) {
    asm("mov.b64 {%0,%1},%2;" : "=f"(lo), "=f"(hi) : "l"(v));
}
__device__ __forceinline__ ull ffma2(ull a, ull b, ull c) {
    ull d;
    asm("fma.rn.f32x2 %0,%1,%2,%3;" : "=l"(d) : "l"(a), "l"(b), "l"(c));
    return d;
}
__device__ __forceinline__ float fast_ex2(float x) {
    float r; asm("ex2.approx.f32 %0,%1;" : "=f"(r) : "f"(x)); return r;
}
__device__ __forceinline__ float fast_rcp(float x) {
    float r; asm("rcp.approx.f32 %0,%1;" : "=f"(r) : "f"(x)); return r;
}
__device__ __forceinline__ float fsigmoid(float x) {
    return fast_rcp(1.0f + fast_ex2(-1.44269504f * x));
}
__device__ __forceinline__ float ftanh(float x) {
    float ax = fabsf(x);
    float t  = fast_ex2(-2.88539008f * ax);          // exp(-2|x|)
    float y  = (1.0f - t) * fast_rcp(1.0f + t);
    return copysignf(y, x);
}

// ---------------------------------------------------------------------------
// Fused 2-layer GRU, 9-slot decomposition. Grid 128 x 576; CTA owns 4 rows.
// Thread = (slot = tx>>6, j = tx&63). Slot -> one gate row of one matrix:
//   0..2 : W_hh0 gates r,z,n     3..5 : W_ih1 gates r,z,n
//   6..8 : W_hh1 gates r,z,n
// Phase A (step s): each thread dots its 64-wide gate row against 4 batch
// rows (slots 0..5 read h1[s-1]; 6..8 read h2[s-2]); layer-0 x-projection and
// all biases folded in; results -> sh_p[slot][row][j]. No shuffles.
// Phase B: 512 threads each do ONE gate combine (h1[s] and h2[s-1]); h2 also
// streams to global output. Two barriers/step, 1025 steps.
// ---------------------------------------------------------------------------
__global__ void __launch_bounds__(576, 1) gru_fused(
    const float* __restrict__ x,
    const float* __restrict__ W_ih0, const float* __restrict__ W_hh0,
    const float* __restrict__ b_ih0, const float* __restrict__ b_hh0,
    const float* __restrict__ W_ih1, const float* __restrict__ W_hh1,
    const float* __restrict__ b_ih1, const float* __restrict__ b_hh1,
    float* __restrict__ outp,        // (B,T,64)
    float* __restrict__ finalp)      // (B,64)
{
    __shared__ float sh_h1[2][R][64];     // [parity][row][k]
    __shared__ float sh_h2[2][R][64];
    __shared__ float sh_p [9][R][64];     // phase-A slot outputs
    __shared__ float sh_px0[R][64];       // layer-0 n-gate input-side part
    __shared__ float sh_x [2][R][3];      // staged x[t]

    const int tx   = threadIdx.x;
    const int slot = tx >> 6;             // 0..8
    const int j    = tx & 63;

    // ---- weight row (one gate of one matrix), packed f32x2 ----
    const float* __restrict__ Wm =
        (slot < 3) ? W_hh0 : (slot < 6) ? W_ih1 : W_hh1;
    const int gate = slot - ((slot < 3) ? 0 : (slot < 6) ? 3 : 6);  // 0..2
    const int g    = gate * 64 + j;
    ull w2[32];
    const ull* __restrict__ Wll = reinterpret_cast<const ull*>(Wm);
#pragma unroll
    for (int i = 0; i < 32; i++) w2[i] = Wll[g * 32 + i];

    // ---- folded biases + layer-0 input weights ----
    float wx0 = 0.f, wx1 = 0.f, wx2 = 0.f;   // W_ih0 row (slots 0..2)
    float badd = 0.f, bxn = 0.f;
    switch (slot) {
        case 0: badd = b_ih0[j]       + b_hh0[j];        break;
        case 1: badd = b_ih0[j + 64]  + b_hh0[j + 64];   break;
        case 2: badd = b_hh0[j + 128]; bxn = b_ih0[j + 128]; break;
        case 3: badd = b_ih1[j]       + b_hh1[j];        break;
        case 4: badd = b_ih1[j + 64]  + b_hh1[j + 64];   break;
        case 5: badd = b_ih1[j + 128];                   break;
        case 8: badd = b_hh1[j + 128];                   break;
        default: break;                                   // 6,7: 0
    }
    if (slot < 3) {
        wx0 = W_ih0[g * 3 + 0];
        wx1 = W_ih0[g * 3 + 1];
        wx2 = W_ih0[g * 3 + 2];
    }

    // phase-B task: (layer L, row r, unit j2) for tx < 512
    const int L  = tx >> 8;
    const int r2 = (tx >> 6) & 3;
    const int j2 = j;

    // x-staging task: slot 8, j < 12 -> (row xr, comp xc)
    const int xr = j / 3, xc = j - 3 * xr;
    const bool xstage = (slot == 8) && (j < 12);

    // ---- init: zero both parities of both states; prestage x[0] ----
    for (int i = tx; i < 2 * R * 64; i += 576) {
        reinterpret_cast<float*>(sh_h1)[i] = 0.f;
        reinterpret_cast<float*>(sh_h2)[i] = 0.f;
    }
    const int row4 = blockIdx.x * 4;
    if (xstage)
        sh_x[0][xr][xc] = __ldg(&x[((size_t)(row4 + xr) * Tsz) * 3 + xc]);
    __syncthreads();

    for (int s = 0; s <= Tsz; s++) {
        const int par = s & 1;

        // ================= phase A: 9 GEMV slices ========================
        const float* __restrict__ hsrc =
            (slot < 6) ? &sh_h1[par][0][0] : &sh_h2[par][0][0];
#pragma unroll
        for (int r = 0; r < R; r++) {
            const ulonglong2* __restrict__ hb =
                reinterpret_cast<const ulonglong2*>(hsrc + r * 64);
            ull a0 = 0ull, a1 = 0ull;
#pragma unroll
            for (int i = 0; i < 16; i++) {
                const ulonglong2 h4 = hb[i];        // warp-uniform -> broadcast
                a0 = ffma2(h4.x, w2[2 * i],     a0);
                a1 = ffma2(h4.y, w2[2 * i + 1], a1);
            }
            float l0, h0, l1, h1;
            unpack2(a0, l0, h0); unpack2(a1, l1, h1);
            float p = ((l0 + h0) + (l1 + h1)) + badd;
            if (slot < 3) {
                const float xv0 = sh_x[par][r][0];
                const float xv1 = sh_x[par][r][1];
                const float xv2 = sh_x[par][r][2];
                const float xp = fmaf(xv2, wx2, fmaf(xv1, wx1, xv0 * wx0));
                if (slot == 2) {
                    sh_px0[r][j] = bxn + xp;        // input-side n (outside r*)
                } else {
                    p += xp;
                }
            }
            sh_p[slot][r][j] = p;
        }
        __syncthreads();

        // ================= phase B: gate combines (all warps) ============
        if (tx < 512) {
            if (L == 0) {
                if (s < Tsz) {                       // h1[s]
                    const float ar  = sh_p[0][r2][j2];
                    const float az  = sh_p[1][r2][j2];
                    const float anr = sh_p[2][r2][j2];
                    const float xan = sh_px0[r2][j2];
                    const float hp  = sh_h1[par][r2][j2];
                    const float rr = fsigmoid(ar);
                    const float zz = fsigmoid(az);
                    const float nn = ftanh(fmaf(rr, anr, xan));
                    sh_h1[par ^ 1][r2][j2] = fmaf(zz, hp - nn, nn);
                }
            } else {
                if (s >= 1) {                        // h2[s-1] -> output
                    const int tau = s - 1;
                    const float ar  = sh_p[3][r2][j2] + sh_p[6][r2][j2];
                    const float az  = sh_p[4][r2][j2] + sh_p[7][r2][j2];
                    const float xan = sh_p[5][r2][j2];
                    const float anr = sh_p[8][r2][j2];
                    const float hp  = sh_h2[par][r2][j2];
                    const float rr = fsigmoid(ar);
                    const float zz = fsigmoid(az);
                    const float nn = ftanh(fmaf(rr, anr, xan));
                    const float hn = fmaf(zz, hp - nn, nn);
                    sh_h2[par ^ 1][r2][j2] = hn;
                    outp[((size_t)(row4 + r2) * Tsz + tau) * Hs + j2] = hn;
                    if (tau == Tsz - 1)
                        finalp[(row4 + r2) * Hs + j2] = hn;
                }
            }
        } else if (xstage && s + 1 < Tsz) {
            // stage x[s+1] into parity (s+1)&1 (consumed next phase A)
            sh_x[par ^ 1][xr][xc] =
                __ldg(&x[((size_t)(row4 + xr) * Tsz + (s + 1)) * 3 + xc]);
        }
        __syncthreads();
    }
}

// ---------------------------------------------------------------------------
extern "C" void kernel_launch(void* const* d_in, const int* in_sizes, int n_in,
                              void* d_out, int out_size)
{
    (void)in_sizes; (void)n_in; (void)out_size;
    const float* x     = (const float*)d_in[0];
    const float* W_ih0 = (const float*)d_in[1];
    const float* W_hh0 = (const float*)d_in[2];
    const float* b_ih0 = (const float*)d_in[3];
    const float* b_hh0 = (const float*)d_in[4];
    const float* W_ih1 = (const float*)d_in[5];
    const float* W_hh1 = (const float*)d_in[6];
    const float* b_ih1 = (const float*)d_in[7];
    const float* b_hh1 = (const float*)d_in[8];

    float* out    = (float*)d_out;
    float* finalh = out + (size_t)Bsz * Tsz * Hs;

    gru_fused<<<128, 576>>>(x, W_ih0, W_hh0, b_ih0, b_hh0,
                            W_ih1, W_hh1, b_ih1, b_hh1, out, finalh);
}

// round 6
// speedup vs baseline: 1.8365x; 1.3215x over previous
#include <cuda_runtime.h>
#include <cstddef>

namespace {
constexpr int Bsz = 512, Tsz = 1024, Hs = 64, R = 4;
}

using ull = unsigned long long;

__device__ __forceinline__ void unpack2(ull v, float& lo, float& hi) {
    asm("mov.b64 {%0,%1},%2;" : "=f"(lo), "=f"(hi) : "l"(v));
}
__device__ __forceinline__ ull ffma2(ull a, ull b, ull c) {
    ull d;
    asm("fma.rn.f32x2 %0,%1,%2,%3;" : "=l"(d) : "l"(a), "l"(b), "l"(c));
    return d;
}
__device__ __forceinline__ float fast_ex2(float x) {
    float r; asm("ex2.approx.f32 %0,%1;" : "=f"(r) : "f"(x)); return r;
}
__device__ __forceinline__ float fast_rcp(float x) {
    float r; asm("rcp.approx.f32 %0,%1;" : "=f"(r) : "f"(x)); return r;
}
__device__ __forceinline__ float fsigmoid(float x) {
    return fast_rcp(1.0f + fast_ex2(-1.44269504f * x));
}
__device__ __forceinline__ float ftanh(float x) {
    float ax = fabsf(x);
    float t  = fast_ex2(-2.88539008f * ax);          // exp(-2|x|)
    float y  = (1.0f - t) * fast_rcp(1.0f + t);
    return copysignf(y, x);
}

// ---------------------------------------------------------------------------
// Fused 2-layer GRU. Grid 128 x 384; CTA owns 4 batch rows.
// PHASE A (thread = (m = tx>>7, j = (tx&127)>>1, half = tx&1)):
//   each thread dots 3 gate-rows (j, j+64, j+128) of matrix m over its 32-k
//   half against 4 rows: m=0 Whh0.h1[s-1], m=1 Wih1.h1[s-1], m=2 Whh1.h2[s-2].
//   48 packed f32x2 weight regs -> 6 FFMA2 per LDS.128 (3x less smem traffic
//   than one-gate-per-thread). shfl_xor(1) completes each dot; half-0 lanes
//   post sums (+folded biases) to sh_p[m][gate][row][j].
// PHASE B (distributed): 512 combine tasks (2 layers x 4 rows x 64 units) on
//   384 threads (tx<128 take two). Layer-0 tasks also apply the x-projection
//   (9 FMA, weights preloaded for the task's fixed j). h2 streams to output.
// Two barriers per step, Tsz+1 steps, zero global scratch.
// ---------------------------------------------------------------------------
__global__ void __launch_bounds__(384, 1) gru_fused(
    const float* __restrict__ x,
    const float* __restrict__ W_ih0, const float* __restrict__ W_hh0,
    const float* __restrict__ b_ih0, const float* __restrict__ b_hh0,
    const float* __restrict__ W_ih1, const float* __restrict__ W_hh1,
    const float* __restrict__ b_ih1, const float* __restrict__ b_hh1,
    float* __restrict__ outp,        // (B,T,64)
    float* __restrict__ finalp)      // (B,64)
{
    __shared__ float sh_h1[2][R][2][36];   // [parity][row][khalf][32+pad]
    __shared__ float sh_h2[2][R][2][36];
    __shared__ float sh_p [3][3][R][64];   // [matrix][gate][row][j]
    __shared__ float sh_x [2][R][3];       // staged x[t]

    const int tx   = threadIdx.x;
    const int m    = tx >> 7;            // 0: Whh0, 1: Wih1, 2: Whh1
    const int lr   = tx & 127;
    const int half = lr & 1;
    const int j    = lr >> 1;
    const int kb   = half * 32;

    // ---- phase-A weights: 3 gate-rows x 32-k-half, packed f32x2 ----
    const float* __restrict__ Wm = (m == 0) ? W_hh0 : (m == 1) ? W_ih1 : W_hh1;
    ull w2[48];
    const ull* __restrict__ Wll = reinterpret_cast<const ull*>(Wm);
#pragma unroll
    for (int g3 = 0; g3 < 3; g3++) {
        const int g = j + g3 * 64;
#pragma unroll
        for (int kk = 0; kk < 16; kk++)
            w2[g3 * 16 + kk] = Wll[(g * 64 + kb) / 2 + kk];
    }

    // folded biases for the posted dot sums
    float badd0 = 0.f, badd1 = 0.f, badd2 = 0.f;
    if (m == 0) {
        badd0 = b_ih0[j]       + b_hh0[j];
        badd1 = b_ih0[j + 64]  + b_hh0[j + 64];
        badd2 = b_hh0[j + 128];                  // recurrent n (inside r*)
    } else if (m == 1) {
        badd0 = b_ih1[j]       + b_hh1[j];
        badd1 = b_ih1[j + 64]  + b_hh1[j + 64];
        badd2 = b_ih1[j + 128];                  // input n
    } else {
        badd2 = b_hh1[j + 128];                  // recurrent n
    }

    // ---- phase-B tasks: id -> (L = id>>8, r = (id>>6)&3, j = id&63) ----
    const int id1 = tx;                    // 0..383
    const int id2 = tx + 384;              // tx<128 only (L1, rows 2..3)
    const int r1 = (id1 >> 6) & 3, j1 = id1 & 63;
    const int r2 = (id2 >> 6) & 3, j2 = id2 & 63;
    const bool t1L0 = (id1 < 256);         // task1 layer
    const bool dual = (tx < 128);

    float wxa[9], bxn = 0.f;               // layer-0 x-proj weights (task1 L0)
    if (t1L0) {
#pragma unroll
        for (int g3 = 0; g3 < 3; g3++)
#pragma unroll
            for (int c = 0; c < 3; c++)
                wxa[g3 * 3 + c] = W_ih0[(j1 + g3 * 64) * 3 + c];
        bxn = b_ih0[j1 + 128];
    }

    // x staging: threads 128..139 (single-task) prefetch x[s+1]
    const int  sx  = tx - 128;
    const bool xst = (sx >= 0 && sx < 12);
    const int  xr  = xst ? sx / 3 : 0, xc = xst ? sx % 3 : 0;
    const int row4 = blockIdx.x * 4;

    // ---- init: zero state buffers (both parities); prestage x[0] ----
    for (int i = tx; i < 2 * R * 2 * 36; i += 384) {
        reinterpret_cast<float*>(sh_h1)[i] = 0.f;
        reinterpret_cast<float*>(sh_h2)[i] = 0.f;
    }
    if (xst)
        sh_x[0][xr][xc] = __ldg(&x[((size_t)(row4 + xr) * Tsz) * 3 + xc]);
    __syncthreads();

    for (int s = 0; s <= Tsz; s++) {
        const int par = s & 1;

        // ===================== PHASE A: dots =============================
        const float* __restrict__ hsrc =
            (m == 2) ? &sh_h2[par][0][half][0] : &sh_h1[par][0][half][0];
#pragma unroll
        for (int r = 0; r < R; r++) {
            const ulonglong2* __restrict__ hb =
                reinterpret_cast<const ulonglong2*>(hsrc + r * 72);
            ull a0 = 0ull, a1 = 0ull, a2 = 0ull;
#pragma unroll
            for (int i = 0; i < 8; i++) {
                const ulonglong2 h4 = hb[i];               // LDS.128
                a0 = ffma2(h4.x, w2[2 * i],          a0);
                a0 = ffma2(h4.y, w2[2 * i + 1],      a0);
                a1 = ffma2(h4.x, w2[16 + 2 * i],     a1);
                a1 = ffma2(h4.y, w2[16 + 2 * i + 1], a1);
                a2 = ffma2(h4.x, w2[32 + 2 * i],     a2);
                a2 = ffma2(h4.y, w2[32 + 2 * i + 1], a2);
            }
            float l, h;
            unpack2(a0, l, h); float pr = l + h;
            unpack2(a1, l, h); float pz = l + h;
            unpack2(a2, l, h); float pn = l + h;
            pr += __shfl_xor_sync(0xffffffffu, pr, 1);
            pz += __shfl_xor_sync(0xffffffffu, pz, 1);
            pn += __shfl_xor_sync(0xffffffffu, pn, 1);
            if (half == 0) {
                sh_p[m][0][r][j] = pr + badd0;
                sh_p[m][1][r][j] = pz + badd1;
                sh_p[m][2][r][j] = pn + badd2;
            }
        }
        __syncthreads();

        // ===================== PHASE B: combines ==========================
        // task 1
        if (t1L0) {
            if (s < Tsz) {                                 // h1[s]
                const float x0 = sh_x[par][r1][0];
                const float x1 = sh_x[par][r1][1];
                const float x2 = sh_x[par][r1][2];
                const float ar = sh_p[0][0][r1][j1]
                    + fmaf(x2, wxa[2], fmaf(x1, wxa[1], x0 * wxa[0]));
                const float az = sh_p[0][1][r1][j1]
                    + fmaf(x2, wxa[5], fmaf(x1, wxa[4], x0 * wxa[3]));
                const float xan = bxn
                    + fmaf(x2, wxa[8], fmaf(x1, wxa[7], x0 * wxa[6]));
                const float rr = fsigmoid(ar);
                const float zz = fsigmoid(az);
                const float nn = ftanh(fmaf(rr, sh_p[0][2][r1][j1], xan));
                const float hp = sh_h1[par][r1][j1 >> 5][j1 & 31];
                sh_h1[par ^ 1][r1][j1 >> 5][j1 & 31] = fmaf(zz, hp - nn, nn);
            }
        } else {
            if (s >= 1) {                                  // h2[s-1] -> out
                const int tau = s - 1;
                const float ar  = sh_p[1][0][r1][j1] + sh_p[2][0][r1][j1];
                const float az  = sh_p[1][1][r1][j1] + sh_p[2][1][r1][j1];
                const float rr  = fsigmoid(ar);
                const float zz  = fsigmoid(az);
                const float nn  = ftanh(fmaf(rr, sh_p[2][2][r1][j1],
                                                 sh_p[1][2][r1][j1]));
                const float hp  = sh_h2[par][r1][j1 >> 5][j1 & 31];
                const float hn  = fmaf(zz, hp - nn, nn);
                sh_h2[par ^ 1][r1][j1 >> 5][j1 & 31] = hn;
                outp[((size_t)(row4 + r1) * Tsz + tau) * Hs + j1] = hn;
                if (tau == Tsz - 1)
                    finalp[(row4 + r1) * Hs + j1] = hn;
            }
        }
        // task 2 (threads 0..127): layer 1, rows 2..3
        if (dual && s >= 1) {
            const int tau = s - 1;
            const float ar  = sh_p[1][0][r2][j2] + sh_p[2][0][r2][j2];
            const float az  = sh_p[1][1][r2][j2] + sh_p[2][1][r2][j2];
            const float rr  = fsigmoid(ar);
            const float zz  = fsigmoid(az);
            const float nn  = ftanh(fmaf(rr, sh_p[2][2][r2][j2],
                                             sh_p[1][2][r2][j2]));
            const float hp  = sh_h2[par][r2][j2 >> 5][j2 & 31];
            const float hn  = fmaf(zz, hp - nn, nn);
            sh_h2[par ^ 1][r2][j2 >> 5][j2 & 31] = hn;
            outp[((size_t)(row4 + r2) * Tsz + tau) * Hs + j2] = hn;
            if (tau == Tsz - 1)
                finalp[(row4 + r2) * Hs + j2] = hn;
        }
        // stage x[s+1] for next step's layer-0 combine
        if (xst && s + 1 < Tsz)
            sh_x[par ^ 1][xr][xc] =
                __ldg(&x[((size_t)(row4 + xr) * Tsz + (s + 1)) * 3 + xc]);
        __syncthreads();
    }
}

// ---------------------------------------------------------------------------
extern "C" void kernel_launch(void* const* d_in, const int* in_sizes, int n_in,
                              void* d_out, int out_size)
{
    (void)in_sizes; (void)n_in; (void)out_size;
    const float* x     = (const float*)d_in[0];
    const float* W_ih0 = (const float*)d_in[1];
    const float* W_hh0 = (const float*)d_in[2];
    const float* b_ih0 = (const float*)d_in[3];
    const float* b_hh0 = (const float*)d_in[4];
    const float* W_ih1 = (const float*)d_in[5];
    const float* W_hh1 = (const float*)d_in[6];
    const float* b_ih1 = (const float*)d_in[7];
    const float* b_hh1 = (const float*)d_in[8];

    float* out    = (float*)d_out;
    float* finalh = out + (size_t)Bsz * Tsz * Hs;

    gru_fused<<<128, 384>>>(x, W_ih0, W_hh0, b_ih0, b_hh0,
                            W_ih1, W_hh1, b_ih1, b_hh1, out, finalh);
}